// round 1
// baseline (speedup 1.0000x reference)
#include <cuda_runtime.h>

// Problem constants (fixed shapes per reference)
#define N0 8000
#define N1 4000
#define N2 2000
#define DIM 128
#define BCOLS 384   // 3 * DIM concatenated

#define B0_OFF 0
#define B1_OFF (N0 * BCOLS)
#define B2_OFF ((N0 + N1) * BCOLS)
#define TOTAL_ROWS (N0 + N1 + N2)

// Scratch: concatenated routed-inputs B and GEMM result T
__device__ float g_B[TOTAL_ROWS * BCOLS];
__device__ float g_T[TOTAL_ROWS * BCOLS];

// ---------------------------------------------------------------------------
// build1: fill B with copies / gathers / zeros (scatter targets zeroed here)
//   B0 = [h0 | 0 | 0]          (scatters fill later)
//   B1 = [h0[idx0] | h1 | 0]
//   B2 = [h0[idx0[idx1]] | h1[idx1] | h2]
// ---------------------------------------------------------------------------
__global__ void build1_kernel(const float* __restrict__ h0,
                              const float* __restrict__ h1,
                              const float* __restrict__ h2,
                              const int* __restrict__ idx0,
                              const int* __restrict__ idx1) {
    int i = blockIdx.x * blockDim.x + threadIdx.x;
    if (i < N0 * BCOLS) {
        int r = i / BCOLS, c = i % BCOLS;
        g_B[B0_OFF + i] = (c < DIM) ? h0[r * DIM + c] : 0.0f;
        return;
    }
    i -= N0 * BCOLS;
    if (i < N1 * BCOLS) {
        int r = i / BCOLS, c = i % BCOLS;
        float v;
        if (c < DIM)          v = h0[idx0[r] * DIM + c];
        else if (c < 2 * DIM) v = h1[r * DIM + (c - DIM)];
        else                  v = 0.0f;
        g_B[B1_OFF + i] = v;
        return;
    }
    i -= N1 * BCOLS;
    if (i < N2 * BCOLS) {
        int r = i / BCOLS, c = i % BCOLS;
        float v;
        if (c < DIM)          v = h0[idx0[idx1[r]] * DIM + c];
        else if (c < 2 * DIM) v = h1[idx1[r] * DIM + (c - DIM)];
        else                  v = h2[r * DIM + (c - 2 * DIM)];
        g_B[B2_OFF + i] = v;
    }
}

// ---------------------------------------------------------------------------
// build2: scatters (indices are unique -> plain stores)
//   B0[idx0[s], DIM:2DIM]        = h1[s]
//   B0[idx0[idx1[s]], 2DIM:3DIM] = h2[s]
//   B1[idx1[s], 2DIM:3DIM]       = h2[s]
// ---------------------------------------------------------------------------
__global__ void build2_kernel(const float* __restrict__ h1,
                              const float* __restrict__ h2,
                              const int* __restrict__ idx0,
                              const int* __restrict__ idx1) {
    int i = blockIdx.x * blockDim.x + threadIdx.x;
    if (i < N1 * DIM) {
        int s = i / DIM, c = i % DIM;
        g_B[B0_OFF + idx0[s] * BCOLS + DIM + c] = h1[i];
        return;
    }
    i -= N1 * DIM;
    if (i < N2 * DIM) {
        int s = i / DIM, c = i % DIM;
        g_B[B0_OFF + idx0[idx1[s]] * BCOLS + 2 * DIM + c] = h2[i];
        return;
    }
    i -= N2 * DIM;
    if (i < N2 * DIM) {
        int s = i / DIM, c = i % DIM;
        g_B[B1_OFF + idx1[s] * BCOLS + 2 * DIM + c] = h2[i];
    }
}

// ---------------------------------------------------------------------------
// gemm_all: T_i = adj_i @ B_i for all 3 levels, single flattened grid.
// 128x128 tile, BK=8, 256 threads, 8x8 per thread (split 4+4 fragments).
// Levels: 63*3 + 32*3 + 16*3 = 189 + 96 + 48 = 333 blocks.
// ---------------------------------------------------------------------------
#define GEMM_BLOCKS 333

__global__ __launch_bounds__(256) void gemm_all_kernel(
    const float* __restrict__ adj0,
    const float* __restrict__ adj1,
    const float* __restrict__ adj2) {

    int b = blockIdx.x;
    const float* A;
    const float* Bp;
    float* Tp;
    int M, mt, nt;
    if (b < 189) {
        A = adj0; M = N0; Bp = g_B + B0_OFF; Tp = g_T + B0_OFF;
        mt = b / 3; nt = b % 3;
    } else if (b < 285) {
        int bb = b - 189;
        A = adj1; M = N1; Bp = g_B + B1_OFF; Tp = g_T + B1_OFF;
        mt = bb / 3; nt = bb % 3;
    } else {
        int bb = b - 285;
        A = adj2; M = N2; Bp = g_B + B2_OFF; Tp = g_T + B2_OFF;
        mt = bb / 3; nt = bb % 3;
    }

    const int m0 = mt * 128;
    const int n0 = nt * 128;

    __shared__ float As[8][132];  // [k][m], padded
    __shared__ float Bs[8][128];  // [k][n]

    const int tid = threadIdx.x;
    const int ar = tid >> 1;          // 0..127  (A tile row)
    const int ac = (tid & 1) * 4;     // 0 or 4  (A tile k)
    const int br = tid >> 5;          // 0..7    (B tile k)
    const int bc = (tid & 31) * 4;    // 0..124  (B tile n)
    const int tx = tid & 15;
    const int ty = tid >> 4;

    float acc[8][8];
#pragma unroll
    for (int r = 0; r < 8; r++)
#pragma unroll
        for (int c = 0; c < 8; c++) acc[r][c] = 0.0f;

    const int am = m0 + ar;
    const bool avalid = (am < M);
    const float* Arow = A + (size_t)(avalid ? am : 0) * M;

    for (int k0 = 0; k0 < M; k0 += 8) {
        float4 av;
        if (avalid) av = *(const float4*)(Arow + k0 + ac);
        else        av = make_float4(0.f, 0.f, 0.f, 0.f);
        As[ac + 0][ar] = av.x;
        As[ac + 1][ar] = av.y;
        As[ac + 2][ar] = av.z;
        As[ac + 3][ar] = av.w;

        float4 bv = *(const float4*)(Bp + (size_t)(k0 + br) * BCOLS + n0 + bc);
        *(float4*)&Bs[br][bc] = bv;

        __syncthreads();

#pragma unroll
        for (int kk = 0; kk < 8; kk++) {
            float a[8], bb2[8];
#pragma unroll
            for (int r = 0; r < 4; r++) {
                a[r]     = As[kk][ty * 4 + r];
                a[4 + r] = As[kk][64 + ty * 4 + r];
            }
#pragma unroll
            for (int c = 0; c < 4; c++) {
                bb2[c]     = Bs[kk][tx * 4 + c];
                bb2[4 + c] = Bs[kk][64 + tx * 4 + c];
            }
#pragma unroll
            for (int r = 0; r < 8; r++)
#pragma unroll
                for (int c = 0; c < 8; c++)
                    acc[r][c] += a[r] * bb2[c];
        }
        __syncthreads();
    }

    // Epilogue: rows {rh*64 + ty*4 + r}, cols {ch*64 + tx*4 + c}
#pragma unroll
    for (int rh = 0; rh < 2; rh++) {
#pragma unroll
        for (int r = 0; r < 4; r++) {
            int m = m0 + rh * 64 + ty * 4 + r;
            if (m < M) {
                float* Crow = Tp + (size_t)m * BCOLS + n0;
                float4 v0 = make_float4(acc[rh * 4 + r][0], acc[rh * 4 + r][1],
                                        acc[rh * 4 + r][2], acc[rh * 4 + r][3]);
                float4 v1 = make_float4(acc[rh * 4 + r][4], acc[rh * 4 + r][5],
                                        acc[rh * 4 + r][6], acc[rh * 4 + r][7]);
                *(float4*)(Crow + tx * 4)      = v0;
                *(float4*)(Crow + 64 + tx * 4) = v1;
            }
        }
    }
}

// ---------------------------------------------------------------------------
// stagec: out_i[r] = sum_j relu( T_i[r, j*128:(j+1)*128] @ W[i,j] + b[i,j] )
// 32 rows per block in smem, 128 threads (one output column each).
// blocks: 250 + 125 + 63 = 438
// ---------------------------------------------------------------------------
#define STAGEC_BLOCKS 438
#define RB 32

__global__ __launch_bounds__(128) void stagec_kernel(
    const float* __restrict__ Ws,   // [3][3][128][128] (in,out)
    const float* __restrict__ bs,   // [3][3][128]
    float* __restrict__ out) {

    int b = blockIdx.x;
    int level, r0, M;
    const float* Tp;
    size_t outoff;
    if (b < 250) {
        level = 0; r0 = b * RB; M = N0; Tp = g_T + B0_OFF; outoff = 0;
    } else if (b < 375) {
        level = 1; r0 = (b - 250) * RB; M = N1; Tp = g_T + B1_OFF;
        outoff = (size_t)N0 * DIM;
    } else {
        level = 2; r0 = (b - 375) * RB; M = N2; Tp = g_T + B2_OFF;
        outoff = (size_t)(N0 + N1) * DIM;
    }

    __shared__ float Tsh[RB][BCOLS];  // 48 KB

    const int c = threadIdx.x;  // output column 0..127

    for (int t = c; t < RB * BCOLS; t += 128) {
        int rr = t / BCOLS, cc = t % BCOLS;
        int m = r0 + rr;
        Tsh[rr][cc] = (m < M) ? Tp[(size_t)m * BCOLS + cc] : 0.0f;
    }
    __syncthreads();

    float res[RB];
#pragma unroll
    for (int r = 0; r < RB; r++) res[r] = 0.0f;

    for (int j = 0; j < 3; j++) {
        const float* W = Ws + (size_t)(level * 3 + j) * DIM * DIM;  // [k][c]
        float bias = bs[(level * 3 + j) * DIM + c];
        float acc[RB];
#pragma unroll
        for (int r = 0; r < RB; r++) acc[r] = 0.0f;
        for (int k = 0; k < DIM; k++) {
            float w = W[k * DIM + c];
#pragma unroll
            for (int r = 0; r < RB; r++)
                acc[r] += Tsh[r][j * DIM + k] * w;
        }
#pragma unroll
        for (int r = 0; r < RB; r++)
            res[r] += fmaxf(acc[r] + bias, 0.0f);
    }

#pragma unroll
    for (int r = 0; r < RB; r++) {
        int m = r0 + r;
        if (m < M) out[outoff + (size_t)m * DIM + c] = res[r];
    }
}

// ---------------------------------------------------------------------------
// kernel_launch
// Inputs (metadata order): adj0, adj1, adj2, h0, h1, h2, idx0, idx1, Ws, bs
// Output: concat(out0, out1, out2) = (14000*128) float32
// ---------------------------------------------------------------------------
extern "C" void kernel_launch(void* const* d_in, const int* in_sizes, int n_in,
                              void* d_out, int out_size) {
    const float* adj0 = (const float*)d_in[0];
    const float* adj1 = (const float*)d_in[1];
    const float* adj2 = (const float*)d_in[2];
    const float* h0   = (const float*)d_in[3];
    const float* h1   = (const float*)d_in[4];
    const float* h2   = (const float*)d_in[5];
    const int*   idx0 = (const int*)d_in[6];
    const int*   idx1 = (const int*)d_in[7];
    const float* Ws   = (const float*)d_in[8];
    const float* bs   = (const float*)d_in[9];
    float* out = (float*)d_out;

    {
        int total = TOTAL_ROWS * BCOLS;
        build1_kernel<<<(total + 255) / 256, 256>>>(h0, h1, h2, idx0, idx1);
    }
    {
        int total = (N1 + N2 + N2) * DIM;
        build2_kernel<<<(total + 255) / 256, 256>>>(h1, h2, idx0, idx1);
    }
    gemm_all_kernel<<<GEMM_BLOCKS, 256>>>(adj0, adj1, adj2);
    stagec_kernel<<<STAGEC_BLOCKS, 128>>>(Ws, bs, out);
}

// round 3
// speedup vs baseline: 3.5710x; 3.5710x over previous
#include <cuda_runtime.h>
#include <cstdint>

// ---------------------------------------------------------------------------
// Problem constants
// ---------------------------------------------------------------------------
#define N0 8000
#define N1 4000
#define N2 2000
#define DIM 128
#define BCOLS 384

#define BT0_OFF 0
#define BT1_OFF (BCOLS * N0)
#define BT2_OFF (BCOLS * (N0 + N1))

#define T0_OFF 0
#define T1_OFF (N0 * BCOLS)
#define T2_OFF ((N0 + N1) * BCOLS)
#define TOTAL_ROWS (N0 + N1 + N2)

// Bt: per-level column-major B (i.e. B^T, [n][k]);  T: row-major [m][384]
__device__ float g_Bt[BCOLS * TOTAL_ROWS];
__device__ float g_T[TOTAL_ROWS * BCOLS];

// ---------------------------------------------------------------------------
// Helpers (sm_80-compatible PTX only — no tcgen05: harness lowers via
// compute_103 which rejects arch-specific instructions)
// ---------------------------------------------------------------------------
__device__ __forceinline__ uint32_t smem_u32(const void* p) {
    uint32_t a;
    asm("{ .reg .u64 t; cvta.to.shared.u64 t, %1; cvt.u32.u64 %0, t; }"
        : "=r"(a) : "l"(p));
    return a;
}

__device__ __forceinline__ float to_tf32(float x) {
    uint32_t u;
    asm("cvt.rna.tf32.f32 %0, %1;" : "=r"(u) : "f"(x));
    return __uint_as_float(u);
}

__device__ __forceinline__ uint32_t cvt_rna_u(uint32_t x) {
    uint32_t y;
    asm("cvt.rna.tf32.f32 %0, %1;" : "=r"(y) : "f"(__uint_as_float(x)));
    return y;
}

#define CP_ASYNC_CG(dst, src, sz) \
    asm volatile("cp.async.cg.shared.global [%0], [%1], 16, %2;" \
        :: "r"(dst), "l"(src), "r"(sz) : "memory")
#define CP_ASYNC_CG16(dst, src) \
    asm volatile("cp.async.cg.shared.global [%0], [%1], 16;" \
        :: "r"(dst), "l"(src) : "memory")
#define CP_COMMIT() asm volatile("cp.async.commit_group;" ::: "memory")
#define CP_WAIT(n)  asm volatile("cp.async.wait_group " #n ";" ::: "memory")

#define LDSM_X4(r0, r1, r2, r3, addr) \
    asm volatile("ldmatrix.sync.aligned.m8n8.x4.shared.b16 {%0,%1,%2,%3}, [%4];" \
        : "=r"(r0), "=r"(r1), "=r"(r2), "=r"(r3) : "r"(addr))

#define MMA_TF32(c, a, b) \
    asm volatile("mma.sync.aligned.m16n8k8.row.col.f32.tf32.tf32.f32 " \
        "{%0,%1,%2,%3}, {%4,%5,%6,%7}, {%8,%9}, {%0,%1,%2,%3};" \
        : "+f"((c)[0]), "+f"((c)[1]), "+f"((c)[2]), "+f"((c)[3]) \
        : "r"((a)[0]), "r"((a)[1]), "r"((a)[2]), "r"((a)[3]), \
          "r"((b)[0]), "r"((b)[1]))

// Tile rows are 64B (16 floats = 4 chunks of 16B). Chunk swizzle keeps
// ldmatrix 8-row phases on 8 distinct 16B bank-groups.
__device__ __forceinline__ uint32_t tile_off(int row, int chunk) {
    return (uint32_t)(row * 64 + ((chunk ^ ((row >> 1) & 3)) << 4));
}

// ---------------------------------------------------------------------------
// buildA: dense/gather parts of B^T via 32x32 smem transpose (coalesced
// reads from h*, coalesced writes to g_Bt). Zeros where scatters land later.
// grid: 438 r-tiles * 12 n-tiles = 5256 blocks, 256 threads.
// ---------------------------------------------------------------------------
__global__ void buildA_kernel(const float* __restrict__ h0,
                              const float* __restrict__ h1,
                              const float* __restrict__ h2,
                              const int* __restrict__ idx0,
                              const int* __restrict__ idx1) {
    int b = blockIdx.x;
    int nt = b % 12;
    int rb = b / 12;
    int level, r0, M;
    size_t bt_off;
    if (rb < 250)      { level = 0; r0 = rb * 32;        M = N0; bt_off = BT0_OFF; }
    else if (rb < 375) { level = 1; r0 = (rb - 250) * 32; M = N1; bt_off = BT1_OFF; }
    else               { level = 2; r0 = (rb - 375) * 32; M = N2; bt_off = BT2_OFF; }
    int n0 = nt * 32;

    __shared__ float tile[32][33];
    int tx = threadIdx.x & 31;
    int ty = threadIdx.x >> 5;

    for (int rr = ty; rr < 32; rr += 8) {
        int r = r0 + rr;
        int n = n0 + tx;
        float v = 0.0f;
        if (r < M) {
            if (level == 0) {
                if (n < DIM) v = h0[r * DIM + n];
            } else if (level == 1) {
                if (n < DIM)          v = h0[idx0[r] * DIM + n];
                else if (n < 2 * DIM) v = h1[r * DIM + (n - DIM)];
            } else {
                if (n < DIM)          v = h0[idx0[idx1[r]] * DIM + n];
                else if (n < 2 * DIM) v = h1[idx1[r] * DIM + (n - DIM)];
                else                  v = h2[r * DIM + (n - 2 * DIM)];
            }
        }
        tile[rr][tx] = to_tf32(v);
    }
    __syncthreads();

    float* dst = g_Bt + bt_off;
    for (int nn = ty; nn < 32; nn += 8) {
        int r = r0 + tx;
        if (r < M) dst[(size_t)(n0 + nn) * M + r] = tile[tx][nn];
    }
}

// ---------------------------------------------------------------------------
// buildB: scatters (unique indices -> plain stores, transposed target)
// ---------------------------------------------------------------------------
__global__ void buildB_kernel(const float* __restrict__ h1,
                              const float* __restrict__ h2,
                              const int* __restrict__ idx0,
                              const int* __restrict__ idx1) {
    int i = blockIdx.x * blockDim.x + threadIdx.x;
    if (i < N1 * DIM) {
        int s = i >> 7, c = i & 127;
        g_Bt[BT0_OFF + (size_t)(DIM + c) * N0 + idx0[s]] = to_tf32(h1[i]);
        return;
    }
    i -= N1 * DIM;
    if (i < N2 * DIM) {
        int s = i >> 7, c = i & 127;
        g_Bt[BT0_OFF + (size_t)(2 * DIM + c) * N0 + idx0[idx1[s]]] = to_tf32(h2[i]);
        return;
    }
    i -= N2 * DIM;
    if (i < N2 * DIM) {
        int s = i >> 7, c = i & 127;
        g_Bt[BT1_OFF + (size_t)(2 * DIM + c) * N1 + idx1[s]] = to_tf32(h2[i]);
    }
}

// ---------------------------------------------------------------------------
// tc_gemm: T_i = adj_i @ B_i with mma.sync tf32 (m16n8k8).
// CTA tile 128x128, BK=16 double-buffered cp.async; warp tile 64x32.
// Grid: (63 + 32 + 16) * 3 = 333 CTAs, n-minor so adj panels share L2.
// ---------------------------------------------------------------------------
#define GEMM_CTAS 333

__global__ void __launch_bounds__(256, 2) tc_gemm_kernel(
    const float* __restrict__ adj0,
    const float* __restrict__ adj1,
    const float* __restrict__ adj2) {

    __shared__ __align__(16) float sA[2][2048];  // 8 KB per stage
    __shared__ __align__(16) float sB[2][2048];

    const int tid  = threadIdx.x;
    const int lane = tid & 31;
    const int wid  = tid >> 5;
    const int warp_m = wid & 1;   // 0..1 (64 rows each)
    const int warp_n = wid >> 1;  // 0..3 (32 cols each)

    int b = blockIdx.x;
    const float* A;
    const float* Bt;
    float* Tp;
    int M, mt_, nt_;
    if (b < 189)      { A = adj0; Bt = g_Bt + BT0_OFF; Tp = g_T + T0_OFF; M = N0; mt_ = b / 3;         nt_ = b % 3; }
    else if (b < 285) { A = adj1; Bt = g_Bt + BT1_OFF; Tp = g_T + T1_OFF; M = N1; mt_ = (b - 189) / 3; nt_ = (b - 189) % 3; }
    else              { A = adj2; Bt = g_Bt + BT2_OFF; Tp = g_T + T2_OFF; M = N2; mt_ = (b - 285) / 3; nt_ = (b - 285) % 3; }
    const int K  = M;
    const int m0 = mt_ * 128;
    const int n0 = nt_ * 128;

    const uint32_t aBase[2] = { smem_u32(sA[0]), smem_u32(sA[1]) };
    const uint32_t bBase[2] = { smem_u32(sB[0]), smem_u32(sB[1]) };

    // ldmatrix per-thread address components
    const int rlA   = lane & 15;
    const int acoff = lane >> 4;                       // 0/1
    uint32_t aoff[4]; int aswz[4];
#pragma unroll
    for (int mt = 0; mt < 4; mt++) {
        int row = warp_m * 64 + mt * 16 + rlA;
        aoff[mt] = (uint32_t)(row * 64);
        aswz[mt] = (row >> 1) & 3;
    }
    const int rlB   = (lane & 7) | ((lane & 16) >> 1); // 0..15
    const int bcoff = (lane >> 3) & 1;
    uint32_t boff[2]; int bswz[2];
#pragma unroll
    for (int p = 0; p < 2; p++) {
        int row = warp_n * 32 + p * 16 + rlB;
        boff[p] = (uint32_t)(row * 64);
        bswz[p] = (row >> 1) & 3;
    }

    // cp.async per-thread: 2 chunks each for A and B
    int cpm[2], cpc[2];
#pragma unroll
    for (int i = 0; i < 2; i++) {
        int idx = i * 256 + tid;
        cpm[i] = idx >> 2;    // row 0..127
        cpc[i] = idx & 3;     // chunk
    }

    float acc[4][4][4];
#pragma unroll
    for (int mt = 0; mt < 4; mt++)
#pragma unroll
        for (int nt = 0; nt < 4; nt++)
#pragma unroll
            for (int i = 0; i < 4; i++) acc[mt][nt][i] = 0.0f;

    const int nk = K / 16;

    // --- tile loader ---
    auto load_tile = [&](int buf, int it) {
        int k0 = it * 16;
#pragma unroll
        for (int i = 0; i < 2; i++) {
            int m = cpm[i], c = cpc[i];
            // A (guard rows beyond M: zero-fill via src-size 0)
            int gm = m0 + m;
            uint32_t sz = (gm < M) ? 16u : 0u;
            int gms = (gm < M) ? gm : 0;
            const float* srca = A + (size_t)gms * K + k0 + c * 4;
            CP_ASYNC_CG(aBase[buf] + tile_off(m, c), srca, sz);
            // B (always valid: n0+m <= 383, K multiple of 16)
            const float* srcb = Bt + (size_t)(n0 + m) * K + k0 + c * 4;
            CP_ASYNC_CG16(bBase[buf] + tile_off(m, c), srcb);
        }
    };

    load_tile(0, 0);
    CP_COMMIT();

    int buf = 0;
    for (int it = 0; it < nk; ++it) {
        bool more = (it + 1 < nk);
        if (more) { load_tile(buf ^ 1, it + 1); CP_COMMIT(); }
        if (more) { CP_WAIT(1); } else { CP_WAIT(0); }
        __syncthreads();

#pragma unroll
        for (int kh = 0; kh < 2; kh++) {
            uint32_t afr[4][4], bfr[4][2];
#pragma unroll
            for (int mt = 0; mt < 4; mt++) {
                uint32_t addr = aBase[buf] + aoff[mt]
                    + (uint32_t)((((kh << 1) + acoff) ^ aswz[mt]) << 4);
                LDSM_X4(afr[mt][0], afr[mt][1], afr[mt][2], afr[mt][3], addr);
            }
#pragma unroll
            for (int p = 0; p < 2; p++) {
                uint32_t addr = bBase[buf] + boff[p]
                    + (uint32_t)((((kh << 1) + bcoff) ^ bswz[p]) << 4);
                LDSM_X4(bfr[2 * p][0], bfr[2 * p][1],
                        bfr[2 * p + 1][0], bfr[2 * p + 1][1], addr);
            }
            // unbiased tf32 rounding of A (adj is all-positive; truncation
            // would bias the sum ~3e-4)
#pragma unroll
            for (int mt = 0; mt < 4; mt++)
#pragma unroll
                for (int i = 0; i < 4; i++) afr[mt][i] = cvt_rna_u(afr[mt][i]);
#pragma unroll
            for (int mt = 0; mt < 4; mt++)
#pragma unroll
                for (int nt = 0; nt < 4; nt++)
                    MMA_TF32(acc[mt][nt], afr[mt], bfr[nt]);
        }
        __syncthreads();
        buf ^= 1;
    }

    // Epilogue: write to g_T
#pragma unroll
    for (int mt = 0; mt < 4; mt++) {
        int mr = m0 + warp_m * 64 + mt * 16 + (lane >> 2);
#pragma unroll
        for (int nt = 0; nt < 4; nt++) {
            int ng = n0 + warp_n * 32 + nt * 8 + ((lane & 3) << 1);
            if (mr < M) {
                float2 v = make_float2(acc[mt][nt][0], acc[mt][nt][1]);
                *(float2*)(Tp + (size_t)mr * BCOLS + ng) = v;
            }
            if (mr + 8 < M) {
                float2 v = make_float2(acc[mt][nt][2], acc[mt][nt][3]);
                *(float2*)(Tp + (size_t)(mr + 8) * BCOLS + ng) = v;
            }
        }
    }
}

// ---------------------------------------------------------------------------
// stagec: out_i[r] = sum_j relu( T_i[r, j*128:(j+1)*128] @ W[i,j] + b[i,j] )
// ---------------------------------------------------------------------------
#define STAGEC_BLOCKS 438
#define RB 32

__global__ void __launch_bounds__(128) stagec_kernel(
    const float* __restrict__ Ws,
    const float* __restrict__ bs,
    float* __restrict__ out) {

    int b = blockIdx.x;
    int level, r0, M;
    const float* Tp;
    size_t outoff;
    if (b < 250) {
        level = 0; r0 = b * RB; M = N0; Tp = g_T + T0_OFF; outoff = 0;
    } else if (b < 375) {
        level = 1; r0 = (b - 250) * RB; M = N1; Tp = g_T + T1_OFF;
        outoff = (size_t)N0 * DIM;
    } else {
        level = 2; r0 = (b - 375) * RB; M = N2; Tp = g_T + T2_OFF;
        outoff = (size_t)(N0 + N1) * DIM;
    }

    __shared__ float Tsh[RB][BCOLS];  // 48 KB
    const int c = threadIdx.x;

    for (int t = c; t < RB * BCOLS; t += 128) {
        int rr = t / BCOLS, cc = t % BCOLS;
        int m = r0 + rr;
        Tsh[rr][cc] = (m < M) ? Tp[(size_t)m * BCOLS + cc] : 0.0f;
    }
    __syncthreads();

    float res[RB];
#pragma unroll
    for (int r = 0; r < RB; r++) res[r] = 0.0f;

    for (int j = 0; j < 3; j++) {
        const float* W = Ws + (size_t)(level * 3 + j) * DIM * DIM;
        float bias = bs[(level * 3 + j) * DIM + c];
        float acc[RB];
#pragma unroll
        for (int r = 0; r < RB; r++) acc[r] = 0.0f;
#pragma unroll 4
        for (int k = 0; k < DIM; k += 4) {
            float w0 = W[(k + 0) * DIM + c];
            float w1 = W[(k + 1) * DIM + c];
            float w2 = W[(k + 2) * DIM + c];
            float w3 = W[(k + 3) * DIM + c];
#pragma unroll
            for (int r = 0; r < RB; r++) {
                float4 t = *(const float4*)&Tsh[r][j * DIM + k];
                acc[r] += t.x * w0 + t.y * w1 + t.z * w2 + t.w * w3;
            }
        }
#pragma unroll
        for (int r = 0; r < RB; r++)
            res[r] += fmaxf(acc[r] + bias, 0.0f);
    }

#pragma unroll
    for (int r = 0; r < RB; r++) {
        int m = r0 + r;
        if (m < M) out[outoff + (size_t)m * DIM + c] = res[r];
    }
}

// ---------------------------------------------------------------------------
// kernel_launch
// Inputs: adj0, adj1, adj2, h0, h1, h2, idx0, idx1, Ws, bs
// ---------------------------------------------------------------------------
extern "C" void kernel_launch(void* const* d_in, const int* in_sizes, int n_in,
                              void* d_out, int out_size) {
    const float* adj0 = (const float*)d_in[0];
    const float* adj1 = (const float*)d_in[1];
    const float* adj2 = (const float*)d_in[2];
    const float* h0   = (const float*)d_in[3];
    const float* h1   = (const float*)d_in[4];
    const float* h2   = (const float*)d_in[5];
    const int*   idx0 = (const int*)d_in[6];
    const int*   idx1 = (const int*)d_in[7];
    const float* Ws   = (const float*)d_in[8];
    const float* bs   = (const float*)d_in[9];
    float* out = (float*)d_out;

    buildA_kernel<<<438 * 12, 256>>>(h0, h1, h2, idx0, idx1);
    {
        int total = (N1 + N2 + N2) * DIM;
        buildB_kernel<<<(total + 255) / 256, 256>>>(h1, h2, idx0, idx1);
    }
    tc_gemm_kernel<<<GEMM_CTAS, 256>>>(adj0, adj1, adj2);
    stagec_kernel<<<STAGEC_BLOCKS, 128>>>(Ws, bs, out);
}